// round 14
// baseline (speedup 1.0000x reference)
#include <cuda_runtime.h>
#include <math.h>
#include <stdint.h>

#define NB      8
#define NSEQ    256
#define DIMC    512
#define NHEADS  8
#define DH      64
#define NTOK    (NB * NSEQ)       // 2048
#define QKV3    (3 * DIMC)        // 1536
#define SCALE   0.125f            // 64^-0.5

// ---------------- scratch (no cudaMalloc allowed) ----------------
__device__ float g_qkv[NTOK * QKV3];                     // 12.6 MB
__device__ float g_attn[NB * NHEADS * NSEQ * NSEQ];      // 16.8 MB  [b][h][n][m]
__device__ float g_o[NTOK * DIMC];                       // 4 MB     [b][n][h*64+d]

// ---------------- tf32 mma helpers ----------------
__device__ __forceinline__ uint32_t f2tf(float x) {
  uint32_t r;
  asm("cvt.rna.tf32.f32 %0, %1;" : "=r"(r) : "f"(x));
  return r;
}

__device__ __forceinline__ void mma_tf32(float c[4],
    uint32_t a0, uint32_t a1, uint32_t a2, uint32_t a3,
    uint32_t b0, uint32_t b1) {
  asm volatile(
    "mma.sync.aligned.m16n8k8.row.col.f32.tf32.tf32.f32 "
    "{%0,%1,%2,%3}, {%4,%5,%6,%7}, {%8,%9}, {%0,%1,%2,%3};\n"
    : "+f"(c[0]), "+f"(c[1]), "+f"(c[2]), "+f"(c[3])
    : "r"(a0), "r"(a1), "r"(a2), "r"(a3), "r"(b0), "r"(b1));
}

// =================================================================
// tf32 tensor-core GEMM v4: C = A @ B (+bias), optional fused LN on A.
// LN path: block computes stats for its 128 rows in prologue (smem),
// gamma/beta staged in smem, applied during A-staging. Zero extra
// persistent registers (mu/inv only). Requires K == 512 when LNF.
// =================================================================
template<int BN, int WARPS_M, int WARPS_N, bool LNF>
__global__ __launch_bounds__(256) void gemm_tf32(
    const float* __restrict__ A, const float* __restrict__ B,
    const float* __restrict__ bias, float* __restrict__ C,
    const float* __restrict__ gamma, const float* __restrict__ beta,
    int M, int N, int K) {
  constexpr int BM = 128, BK = 16;
  constexpr int WTM = BM / WARPS_M;
  constexpr int WTN = BN / WARPS_N;
  constexpr int MI = WTM / 16;
  constexpr int NI = WTN / 8;
  constexpr int AS = 24;
  constexpr int BS = BN + 8;
  constexpr int BF4 = (BK * BN) / (256 * 4);

  __shared__ uint32_t As[2][BM * AS];
  __shared__ uint32_t Bs[2][BK * BS];
  __shared__ float sLN[LNF ? 1280 : 1];  // mu[128] inv[128] gamma[512] beta[512]

  int t = threadIdx.x;
  int w = t >> 5, l = t & 31;
  int g = l >> 2, tg = l & 3;
  int wm = (w % WARPS_M) * WTM;
  int wn = (w / WARPS_M) * WTN;
  int bm = blockIdx.y * BM, bn = blockIdx.x * BN;

  int arow = t >> 1, akh = (t & 1) * 8;
  const float* Aptr = A + (size_t)(bm + arow) * K + akh;

  if (LNF) {
    // stage gamma/beta
    #pragma unroll
    for (int i = 0; i < 2; ++i) {
      int idx = t + i * 256;
      sLN[256 + idx] = gamma[idx];
      sLN[768 + idx] = beta[idx];
    }
    // stats: 2 threads per row, each sums 256 elems
    int row2 = t >> 1, half = t & 1;
    const float* xr = A + (size_t)(bm + row2) * 512 + half * 256;
    float s = 0.f, sq = 0.f;
    #pragma unroll 8
    for (int j = 0; j < 64; ++j) {
      float4 v = *(const float4*)(xr + j * 4);
      s  += v.x + v.y + v.z + v.w;
      sq += v.x * v.x + v.y * v.y + v.z * v.z + v.w * v.w;
    }
    s  += __shfl_xor_sync(0xffffffffu, s, 1);
    sq += __shfl_xor_sync(0xffffffffu, sq, 1);
    if (half == 0) {
      float mu = s * (1.f / 512.f);
      float var = sq * (1.f / 512.f) - mu * mu;
      sLN[row2] = mu;
      sLN[128 + row2] = rsqrtf(var + 1e-5f);
    }
    __syncthreads();
  }
  float mu = 0.f, invs = 1.f;
  if (LNF) { mu = sLN[arow]; invs = sLN[128 + arow]; }

  int brow[BF4], bcol[BF4];
  #pragma unroll
  for (int j = 0; j < BF4; ++j) {
    int lin = (j * 256 + t) * 4;
    brow[j] = lin / BN;
    bcol[j] = lin % BN;
  }

  float c[MI][NI][4];
  #pragma unroll
  for (int i = 0; i < MI; ++i)
    #pragma unroll
    for (int j = 0; j < NI; ++j)
      #pragma unroll
      for (int q = 0; q < 4; ++q) c[i][j][q] = 0.f;

  float4 av0, av1, bv[BF4];

  auto stageA = [&](int buf, int k0) {
    float4 v0 = av0, v1 = av1;
    if (LNF) {
      float4 g0  = *(const float4*)&sLN[256 + k0 + akh];
      float4 g1  = *(const float4*)&sLN[256 + k0 + akh + 4];
      float4 bb0 = *(const float4*)&sLN[768 + k0 + akh];
      float4 bb1 = *(const float4*)&sLN[768 + k0 + akh + 4];
      v0.x = (v0.x - mu) * invs * g0.x + bb0.x;
      v0.y = (v0.y - mu) * invs * g0.y + bb0.y;
      v0.z = (v0.z - mu) * invs * g0.z + bb0.z;
      v0.w = (v0.w - mu) * invs * g0.w + bb0.w;
      v1.x = (v1.x - mu) * invs * g1.x + bb1.x;
      v1.y = (v1.y - mu) * invs * g1.y + bb1.y;
      v1.z = (v1.z - mu) * invs * g1.z + bb1.z;
      v1.w = (v1.w - mu) * invs * g1.w + bb1.w;
    }
    uint32_t u0 = f2tf(v0.x), u1 = f2tf(v0.y), u2 = f2tf(v0.z), u3 = f2tf(v0.w);
    uint32_t u4 = f2tf(v1.x), u5 = f2tf(v1.y), u6 = f2tf(v1.z), u7 = f2tf(v1.w);
    uint4 w0 = {u0, u4, u1, u5};
    uint4 w1 = {u2, u6, u3, u7};
    uint32_t* as = As[buf] + arow * AS + akh;
    *(uint4*)as = w0;
    *(uint4*)(as + 4) = w1;
  };
  auto stageB = [&](int buf) {
    #pragma unroll
    for (int j = 0; j < BF4; ++j) {
      uint4 bu = {f2tf(bv[j].x), f2tf(bv[j].y), f2tf(bv[j].z), f2tf(bv[j].w)};
      *(uint4*)&Bs[buf][brow[j] * BS + bcol[j]] = bu;
    }
  };

  av0 = *(const float4*)(Aptr);
  av1 = *(const float4*)(Aptr + 4);
  #pragma unroll
  for (int j = 0; j < BF4; ++j)
    bv[j] = *(const float4*)(B + (size_t)brow[j] * N + bn + bcol[j]);
  stageA(0, 0);
  stageB(0);
  __syncthreads();

  int nk = K / BK;
  for (int it = 0; it < nk; ++it) {
    int buf = it & 1;
    bool more = (it + 1 < nk);
    int k0n = (it + 1) * BK;
    if (more) {
      av0 = *(const float4*)(Aptr + k0n);
      av1 = *(const float4*)(Aptr + k0n + 4);
      #pragma unroll
      for (int j = 0; j < BF4; ++j)
        bv[j] = *(const float4*)(B + (size_t)(k0n + brow[j]) * N + bn + bcol[j]);
    }

    #pragma unroll
    for (int kk = 0; kk < BK; kk += 8) {
      uint32_t af[MI][4], bf[NI][2];
      #pragma unroll
      for (int i = 0; i < MI; ++i) {
        const uint32_t* pa = As[buf] + (wm + i * 16 + g) * AS + kk + 2 * tg;
        uint2 p0 = *(const uint2*)pa;
        uint2 p1 = *(const uint2*)(pa + 8 * AS);
        af[i][0] = p0.x;
        af[i][1] = p1.x;
        af[i][2] = p0.y;
        af[i][3] = p1.y;
      }
      #pragma unroll
      for (int j = 0; j < NI; ++j) {
        const uint32_t* pb = Bs[buf] + (kk + tg) * BS + wn + j * 8 + g;
        bf[j][0] = pb[0];
        bf[j][1] = pb[4 * BS];
      }
      #pragma unroll
      for (int i = 0; i < MI; ++i)
        #pragma unroll
        for (int j = 0; j < NI; ++j)
          mma_tf32(c[i][j], af[i][0], af[i][1], af[i][2], af[i][3],
                   bf[j][0], bf[j][1]);
    }

    if (more) {
      int nb = buf ^ 1;
      stageA(nb, k0n);
      stageB(nb);
    }
    __syncthreads();
  }

  #pragma unroll
  for (int i = 0; i < MI; ++i) {
    int r0 = bm + wm + i * 16 + g;
    #pragma unroll
    for (int j = 0; j < NI; ++j) {
      int col = bn + wn + j * 8 + tg * 2;
      float b0 = bias ? bias[col] : 0.f;
      float b1 = bias ? bias[col + 1] : 0.f;
      float2 v0 = {c[i][j][0] + b0, c[i][j][1] + b1};
      float2 v1 = {c[i][j][2] + b0, c[i][j][3] + b1};
      *(float2*)&C[(size_t)r0 * N + col] = v0;
      *(float2*)&C[(size_t)(r0 + 8) * N + col] = v1;
    }
  }
}

// =================================================================
// Fused attention v3b (round-13 winner): n-tile 128, 512 threads,
// 1 wave, smem aliasing, Vt XOR-swizzled staging.
// =================================================================
#define VT_OFF   0
#define UN_OFF   (64 * 264)
#define KS_OFF   UN_OFF
#define QS_OFF   (UN_OFF + 256 * 68)
#define PS_OFF   UN_OFF
#define ATTN_SMEM_WORDS (UN_OFF + 128 * 260)
#define ATTN_SMEM_BYTES (ATTN_SMEM_WORDS * 4)

__global__ __launch_bounds__(512, 1) void attn_kernel() {
  extern __shared__ uint32_t sm[];
  uint32_t* Vt = sm + VT_OFF;     // [d][m^swz(d)]  stride 264
  uint32_t* Ks = sm + KS_OFF;     // [m][d]  stride 68   (phase 1)
  uint32_t* Qs = sm + QS_OFF;     // [n][d]  stride 68   (phase 1)
  float*    Ps = (float*)(sm + PS_OFF);  // [n][m] stride 260 (phase 2)
  uint32_t* PsU = sm + PS_OFF;

  int t = threadIdx.x;
  int b = blockIdx.y >> 3, h = blockIdx.y & 7;
  int n0 = blockIdx.x * 128;
  int w = t >> 5, l = t & 31;
  int g = l >> 2, tg = l & 3;

  const float* qkvb = g_qkv + (size_t)b * NSEQ * QKV3 + h * DH;

  // ---- phase 1 stage: K [m][d], V transposed+swizzled, Q [n][d] ----
  {
    int c16 = t & 15, r16 = t >> 4;   // r16 0..31
    int d0 = c16 * 4;
    int xrv = (c16 & 7) << 2;         // swizzle for rows d0..d0+3
    #pragma unroll
    for (int i = 0; i < 8; ++i) {
      int m = r16 + i * 32;
      const float* rowp = qkvb + (size_t)m * QKV3;
      float4 k4 = *(const float4*)(rowp + DIMC + d0);
      uint4 ku = {f2tf(k4.x), f2tf(k4.y), f2tf(k4.z), f2tf(k4.w)};
      *(uint4*)&Ks[m * 68 + d0] = ku;
      float4 v4 = *(const float4*)(rowp + 2 * DIMC + d0);
      int col = m ^ xrv;
      Vt[(d0 + 0) * 264 + col] = f2tf(v4.x);
      Vt[(d0 + 1) * 264 + col] = f2tf(v4.y);
      Vt[(d0 + 2) * 264 + col] = f2tf(v4.z);
      Vt[(d0 + 3) * 264 + col] = f2tf(v4.w);
    }
    #pragma unroll
    for (int i = 0; i < 4; ++i) {
      int n = r16 + i * 32;
      const float* rowp = qkvb + (size_t)(n0 + n) * QKV3;
      float4 q4 = *(const float4*)(rowp + d0);
      uint4 qu = {f2tf(q4.x), f2tf(q4.y), f2tf(q4.z), f2tf(q4.w)};
      *(uint4*)&Qs[n * 68 + d0] = qu;
    }
  }
  __syncthreads();

  // ---- scores S[128][256] = Q @ K^T ; warp tile 32x64 ----
  int wm = (w >> 2) * 32;
  int wnn = (w & 3) * 64;
  float s[2][8][4];
  #pragma unroll
  for (int i = 0; i < 2; ++i)
    #pragma unroll
    for (int j = 0; j < 8; ++j)
      #pragma unroll
      for (int q = 0; q < 4; ++q) s[i][j][q] = 0.f;

  #pragma unroll
  for (int kk = 0; kk < 64; kk += 8) {
    uint32_t a[2][4], bf[8][2];
    #pragma unroll
    for (int i = 0; i < 2; ++i) {
      int r0 = wm + i * 16;
      a[i][0] = Qs[(r0 + g) * 68 + kk + tg];
      a[i][1] = Qs[(r0 + g + 8) * 68 + kk + tg];
      a[i][2] = Qs[(r0 + g) * 68 + kk + tg + 4];
      a[i][3] = Qs[(r0 + g + 8) * 68 + kk + tg + 4];
    }
    #pragma unroll
    for (int j = 0; j < 8; ++j) {
      int m0 = wnn + j * 8;
      bf[j][0] = Ks[(m0 + g) * 68 + kk + tg];
      bf[j][1] = Ks[(m0 + g) * 68 + kk + tg + 4];
    }
    #pragma unroll
    for (int i = 0; i < 2; ++i)
      #pragma unroll
      for (int j = 0; j < 8; ++j)
        mma_tf32(s[i][j], a[i][0], a[i][1], a[i][2], a[i][3],
                 bf[j][0], bf[j][1]);
  }
  __syncthreads();   // Ks/Qs reads done; safe to overwrite with Ps

  #pragma unroll
  for (int i = 0; i < 2; ++i) {
    int r0 = wm + i * 16 + g;
    #pragma unroll
    for (int j = 0; j < 8; ++j) {
      int cc = wnn + j * 8 + tg * 2;
      Ps[r0 * 260 + cc]           = s[i][j][0] * SCALE;
      Ps[r0 * 260 + cc + 1]       = s[i][j][1] * SCALE;
      Ps[(r0 + 8) * 260 + cc]     = s[i][j][2] * SCALE;
      Ps[(r0 + 8) * 260 + cc + 1] = s[i][j][3] * SCALE;
    }
  }
  __syncthreads();

  // ---- softmax: 8 rows per warp; attn -> g_attn (fp32) + Ps (tf32) ----
  {
    #pragma unroll
    for (int r = 0; r < 8; ++r) {
      int n = w * 8 + r;
      float* row = &Ps[n * 260];
      float vals[8];
      float vmax = -1e30f;
      #pragma unroll
      for (int i = 0; i < 8; ++i) {
        vals[i] = row[l + i * 32];
        vmax = fmaxf(vmax, vals[i]);
      }
      #pragma unroll
      for (int o = 16; o; o >>= 1)
        vmax = fmaxf(vmax, __shfl_xor_sync(0xffffffffu, vmax, o));
      float ssum = 0.f;
      #pragma unroll
      for (int i = 0; i < 8; ++i) { vals[i] = __expf(vals[i] - vmax); ssum += vals[i]; }
      #pragma unroll
      for (int o = 16; o; o >>= 1) ssum += __shfl_xor_sync(0xffffffffu, ssum, o);
      float inv = 1.f / ssum;
      float* gA = &g_attn[((size_t)(b * 8 + h) * 256 + n0 + n) * 256];
      #pragma unroll
      for (int i = 0; i < 8; ++i) {
        float a = vals[i] * inv;
        gA[l + i * 32] = a;
        PsU[n * 260 + l + i * 32] = f2tf(a);
      }
    }
  }
  __syncthreads();

  // ---- O[128][64] = P @ V ; warp tile 32x16 (Vt reads de-swizzled) ----
  {
    int wd = (w & 3) * 16;
    float oc[2][2][4];
    #pragma unroll
    for (int i = 0; i < 2; ++i)
      #pragma unroll
      for (int j = 0; j < 2; ++j)
        #pragma unroll
        for (int q = 0; q < 4; ++q) oc[i][j][q] = 0.f;

    #pragma unroll 4
    for (int kk = 0; kk < 256; kk += 8) {
      uint32_t a[2][4], bf[2][2];
      #pragma unroll
      for (int i = 0; i < 2; ++i) {
        int r0 = wm + i * 16;
        a[i][0] = PsU[(r0 + g) * 260 + kk + tg];
        a[i][1] = PsU[(r0 + g + 8) * 260 + kk + tg];
        a[i][2] = PsU[(r0 + g) * 260 + kk + tg + 4];
        a[i][3] = PsU[(r0 + g + 8) * 260 + kk + tg + 4];
      }
      #pragma unroll
      for (int j = 0; j < 2; ++j) {
        int dr = wd + j * 8 + g;
        int xr = ((dr >> 2) & 7) << 2;
        bf[j][0] = Vt[dr * 264 + ((kk + tg) ^ xr)];
        bf[j][1] = Vt[dr * 264 + ((kk + tg + 4) ^ xr)];
      }
      #pragma unroll
      for (int i = 0; i < 2; ++i)
        #pragma unroll
        for (int j = 0; j < 2; ++j)
          mma_tf32(oc[i][j], a[i][0], a[i][1], a[i][2], a[i][3],
                   bf[j][0], bf[j][1]);
    }
    #pragma unroll
    for (int i = 0; i < 2; ++i) {
      int n = n0 + wm + i * 16 + g;
      #pragma unroll
      for (int j = 0; j < 2; ++j) {
        int dd = h * 64 + wd + j * 8 + tg * 2;
        float2 v0 = {oc[i][j][0], oc[i][j][1]};
        float2 v1 = {oc[i][j][2], oc[i][j][3]};
        *(float2*)&g_o[(size_t)(b * 256 + n) * 512 + dd] = v0;
        *(float2*)&g_o[(size_t)(b * 256 + n + 8) * 512 + dd] = v1;
      }
    }
  }
}

// =================================================================
// rpos v5 (scalar, proven): g_o += Σ_m attn * T[idx[n,m]]
// =================================================================
__global__ __launch_bounds__(256) void rpos_kernel(
    const float* __restrict__ table, const int* __restrict__ idx_map) {
  int n = blockIdx.x, h = blockIdx.y;
  __shared__ float sAT[256][12];     // [m][b], padded stride 12
  __shared__ int   sIdx[256];
  __shared__ float sPart[8][8][64];  // [warp][b][d]

  int t = threadIdx.x;
  sIdx[t] = idx_map[n * 256 + t];
  #pragma unroll
  for (int b = 0; b < 8; ++b)
    sAT[t][b] = g_attn[((size_t)(b * 8 + h) * 256 + n) * 256 + t];
  __syncthreads();

  int w = t >> 5, l = t & 31;
  int hw = l >> 4, dl = l & 15;
  int base = w * 32 + hw;

  float acc[8][4];
  #pragma unroll
  for (int b = 0; b < 8; ++b)
    #pragma unroll
    for (int q = 0; q < 4; ++q) acc[b][q] = 0.f;

  const float* tb = table + h * DH + dl * 4;

  float4 buf[4];
  #pragma unroll
  for (int i = 0; i < 4; ++i)
    buf[i] = *(const float4*)&tb[(size_t)sIdx[base + 2 * i] * DIMC];

  #pragma unroll
  for (int i = 0; i < 16; ++i) {
    float4 tv = buf[i & 3];
    if (i + 4 < 16)
      buf[i & 3] = *(const float4*)&tb[(size_t)sIdx[base + 2 * (i + 4)] * DIMC];
    int m = base + 2 * i;
    float4 aa0 = *(const float4*)&sAT[m][0];
    float4 aa1 = *(const float4*)&sAT[m][4];
    acc[0][0] += aa0.x * tv.x; acc[0][1] += aa0.x * tv.y;
    acc[0][2] += aa0.x * tv.z; acc[0][3] += aa0.x * tv.w;
    acc[1][0] += aa0.y * tv.x; acc[1][1] += aa0.y * tv.y;
    acc[1][2] += aa0.y * tv.z; acc[1][3] += aa0.y * tv.w;
    acc[2][0] += aa0.z * tv.x; acc[2][1] += aa0.z * tv.y;
    acc[2][2] += aa0.z * tv.z; acc[2][3] += aa0.z * tv.w;
    acc[3][0] += aa0.w * tv.x; acc[3][1] += aa0.w * tv.y;
    acc[3][2] += aa0.w * tv.z; acc[3][3] += aa0.w * tv.w;
    acc[4][0] += aa1.x * tv.x; acc[4][1] += aa1.x * tv.y;
    acc[4][2] += aa1.x * tv.z; acc[4][3] += aa1.x * tv.w;
    acc[5][0] += aa1.y * tv.x; acc[5][1] += aa1.y * tv.y;
    acc[5][2] += aa1.y * tv.z; acc[5][3] += aa1.y * tv.w;
    acc[6][0] += aa1.z * tv.x; acc[6][1] += aa1.z * tv.y;
    acc[6][2] += aa1.z * tv.z; acc[6][3] += aa1.z * tv.w;
    acc[7][0] += aa1.w * tv.x; acc[7][1] += aa1.w * tv.y;
    acc[7][2] += aa1.w * tv.z; acc[7][3] += aa1.w * tv.w;
  }

  #pragma unroll
  for (int b = 0; b < 8; ++b)
    #pragma unroll
    for (int q = 0; q < 4; ++q)
      acc[b][q] += __shfl_xor_sync(0xffffffffu, acc[b][q], 16);

  if (hw == 0) {
    #pragma unroll
    for (int b = 0; b < 8; ++b) {
      float4 v = {acc[b][0], acc[b][1], acc[b][2], acc[b][3]};
      *(float4*)&sPart[w][b][dl * 4] = v;
    }
  }
  __syncthreads();

  #pragma unroll
  for (int o = t; o < 512; o += 256) {
    int b = o >> 6, d = o & 63;
    float s2 = 0.f;
    #pragma unroll
    for (int w2 = 0; w2 < 8; ++w2) s2 += sPart[w2][b][d];
    g_o[(size_t)(b * 256 + n) * 512 + h * 64 + d] += s2;
  }
}

// =================================================================
extern "C" void kernel_launch(void* const* d_in, const int* in_sizes, int n_in,
                              void* d_out, int out_size) {
  const float* x      = (const float*)d_in[0];
  const float* ln_g   = (const float*)d_in[1];
  const float* ln_b   = (const float*)d_in[2];
  const float* w_qkv  = (const float*)d_in[3];
  const float* table  = (const float*)d_in[4];
  const float* w_out  = (const float*)d_in[5];
  const float* b_out  = (const float*)d_in[6];
  const int*   idxmap = (const int*)d_in[7];
  float* out = (float*)d_out;

  cudaFuncSetAttribute(attn_kernel, cudaFuncAttributeMaxDynamicSharedMemorySize,
                       ATTN_SMEM_BYTES);

  void *p_qkv, *p_o;
  cudaGetSymbolAddress(&p_qkv, g_qkv);
  cudaGetSymbolAddress(&p_o, g_o);

  // 1. qkv = LN(x) @ w_qkv   (2048 x 1536 x 512), fused LN, BN=128
  gemm_tf32<128, 2, 4, true><<<dim3(QKV3 / 128, NTOK / 128), 256>>>(
      x, w_qkv, nullptr, (float*)p_qkv, ln_g, ln_b, NTOK, QKV3, DIMC);

  // 2. attention (scores, softmax, attn·V), n-tile 128 -> 1 wave
  attn_kernel<<<dim3(2, NB * NHEADS), 512, ATTN_SMEM_BYTES>>>();

  // 3. relative-position contribution (scalar v5)
  rpos_kernel<<<dim3(NSEQ, NHEADS), 256>>>(table, idxmap);

  // 4. out = g_o @ w_out + b_out   (2048 x 512 x 512), BN=64
  gemm_tf32<64, 4, 2, false><<<dim3(DIMC / 64, NTOK / 128), 256>>>(
      (const float*)p_o, w_out, b_out, out, nullptr, nullptr,
      NTOK, DIMC, DIMC);
}

// round 15
// speedup vs baseline: 1.1781x; 1.1781x over previous
#include <cuda_runtime.h>
#include <math.h>
#include <stdint.h>

#define NB      8
#define NSEQ    256
#define DIMC    512
#define NHEADS  8
#define DH      64
#define NTOK    (NB * NSEQ)       // 2048
#define QKV3    (3 * DIMC)        // 1536
#define SCALE   0.125f            // 64^-0.5

// ---------------- scratch (no cudaMalloc allowed) ----------------
__device__ float g_xn[NTOK * DIMC];                      // 4 MB
__device__ float g_qkv[NTOK * QKV3];                     // 12.6 MB
__device__ float g_attn[NB * NHEADS * NSEQ * NSEQ];      // 16.8 MB  [b][h][n][m]
__device__ float g_o[NTOK * DIMC];                       // 4 MB     [b][n][h*64+d]

// ---------------- tf32 mma helpers ----------------
__device__ __forceinline__ uint32_t f2tf(float x) {
  uint32_t r;
  asm("cvt.rna.tf32.f32 %0, %1;" : "=r"(r) : "f"(x));
  return r;
}

__device__ __forceinline__ void mma_tf32(float c[4],
    uint32_t a0, uint32_t a1, uint32_t a2, uint32_t a3,
    uint32_t b0, uint32_t b1) {
  asm volatile(
    "mma.sync.aligned.m16n8k8.row.col.f32.tf32.tf32.f32 "
    "{%0,%1,%2,%3}, {%4,%5,%6,%7}, {%8,%9}, {%0,%1,%2,%3};\n"
    : "+f"(c[0]), "+f"(c[1]), "+f"(c[2]), "+f"(c[3])
    : "r"(a0), "r"(a1), "r"(a2), "r"(a3), "r"(b0), "r"(b1));
}

// =================================================================
// LayerNorm: one block per (b,n) row, 256 threads, 2 elems/thread
// =================================================================
__global__ void ln_kernel(const float* __restrict__ x,
                          const float* __restrict__ gamma,
                          const float* __restrict__ beta) {
  int row = blockIdx.x;
  int t = threadIdx.x;
  const float* xr = x + (size_t)row * DIMC;
  float v0 = xr[t], v1 = xr[t + 256];

  __shared__ float red[8];
  __shared__ float stat;

  float s = v0 + v1;
  #pragma unroll
  for (int o = 16; o; o >>= 1) s += __shfl_xor_sync(0xffffffffu, s, o);
  if ((t & 31) == 0) red[t >> 5] = s;
  __syncthreads();
  if (t < 32) {
    float z = (t < 8) ? red[t] : 0.f;
    #pragma unroll
    for (int o = 4; o; o >>= 1) z += __shfl_xor_sync(0xffffffffu, z, o);
    if (t == 0) stat = z * (1.f / DIMC);
  }
  __syncthreads();
  float mean = stat;
  __syncthreads();

  float d0 = v0 - mean, d1 = v1 - mean;
  float vs = d0 * d0 + d1 * d1;
  #pragma unroll
  for (int o = 16; o; o >>= 1) vs += __shfl_xor_sync(0xffffffffu, vs, o);
  if ((t & 31) == 0) red[t >> 5] = vs;
  __syncthreads();
  if (t < 32) {
    float z = (t < 8) ? red[t] : 0.f;
    #pragma unroll
    for (int o = 4; o; o >>= 1) z += __shfl_xor_sync(0xffffffffu, z, o);
    if (t == 0) stat = rsqrtf(z * (1.f / DIMC) + 1e-5f);
  }
  __syncthreads();
  float inv = stat;

  float* xo = g_xn + (size_t)row * DIMC;
  xo[t]       = d0 * inv * gamma[t]       + beta[t];
  xo[t + 256] = d1 * inv * gamma[t + 256] + beta[t + 256];
}

// =================================================================
// tf32 tensor-core GEMM v5: C[M,N] = A[M,K] @ B[K,N] (+bias)
// Template BM (128 or 64). Permuted-k A layout, LDS.64 frags,
// STS.128 staging, double buffer. BM=64: A staged by threads t<128
// (2 blocks/SM for occupancy on small grids).
// =================================================================
template<int BM, int BN, int WARPS_M, int WARPS_N>
__global__ __launch_bounds__(256) void gemm_tf32(
    const float* __restrict__ A, const float* __restrict__ B,
    const float* __restrict__ bias, float* __restrict__ C,
    int M, int N, int K) {
  constexpr int BK = 16;
  constexpr int WTM = BM / WARPS_M;
  constexpr int WTN = BN / WARPS_N;
  constexpr int MI = WTM / 16;
  constexpr int NI = WTN / 8;
  constexpr int AS = 24;
  constexpr int BS = BN + 8;
  constexpr int BF4 = (BK * BN) / (256 * 4);
  constexpr bool AHALF = (BM == 64);   // only t<128 stage A

  __shared__ uint32_t As[2][BM * AS];
  __shared__ uint32_t Bs[2][BK * BS];

  int t = threadIdx.x;
  int w = t >> 5, l = t & 31;
  int g = l >> 2, tg = l & 3;
  int wm = (w % WARPS_M) * WTM;
  int wn = (w / WARPS_M) * WTN;
  int bm = blockIdx.y * BM, bn = blockIdx.x * BN;

  int arow = t >> 1, akh = (t & 1) * 8;
  bool aact = !AHALF || (t < 128);
  if (AHALF && !aact) arow = 0;        // safe dummy
  const float* Aptr = A + (size_t)(bm + arow) * K + akh;

  int brow[BF4], bcol[BF4];
  #pragma unroll
  for (int j = 0; j < BF4; ++j) {
    int lin = (j * 256 + t) * 4;
    brow[j] = lin / BN;
    bcol[j] = lin % BN;
  }

  float c[MI][NI][4];
  #pragma unroll
  for (int i = 0; i < MI; ++i)
    #pragma unroll
    for (int j = 0; j < NI; ++j)
      #pragma unroll
      for (int q = 0; q < 4; ++q) c[i][j][q] = 0.f;

  float4 av0, av1, bv[BF4];

  auto loadA = [&](int k0) {
    if (aact) {
      av0 = *(const float4*)(Aptr + k0);
      av1 = *(const float4*)(Aptr + k0 + 4);
    }
  };
  auto stageA = [&](int buf) {
    if (aact) {
      uint32_t u0 = f2tf(av0.x), u1 = f2tf(av0.y), u2 = f2tf(av0.z), u3 = f2tf(av0.w);
      uint32_t u4 = f2tf(av1.x), u5 = f2tf(av1.y), u6 = f2tf(av1.z), u7 = f2tf(av1.w);
      uint4 w0 = {u0, u4, u1, u5};
      uint4 w1 = {u2, u6, u3, u7};
      uint32_t* as = As[buf] + arow * AS + akh;
      *(uint4*)as = w0;
      *(uint4*)(as + 4) = w1;
    }
  };
  auto stageB = [&](int buf) {
    #pragma unroll
    for (int j = 0; j < BF4; ++j) {
      uint4 bu = {f2tf(bv[j].x), f2tf(bv[j].y), f2tf(bv[j].z), f2tf(bv[j].w)};
      *(uint4*)&Bs[buf][brow[j] * BS + bcol[j]] = bu;
    }
  };

  loadA(0);
  #pragma unroll
  for (int j = 0; j < BF4; ++j)
    bv[j] = *(const float4*)(B + (size_t)brow[j] * N + bn + bcol[j]);
  stageA(0);
  stageB(0);
  __syncthreads();

  int nk = K / BK;
  for (int it = 0; it < nk; ++it) {
    int buf = it & 1;
    bool more = (it + 1 < nk);
    if (more) {
      int k0 = (it + 1) * BK;
      loadA(k0);
      #pragma unroll
      for (int j = 0; j < BF4; ++j)
        bv[j] = *(const float4*)(B + (size_t)(k0 + brow[j]) * N + bn + bcol[j]);
    }

    #pragma unroll
    for (int kk = 0; kk < BK; kk += 8) {
      uint32_t af[MI][4], bf[NI][2];
      #pragma unroll
      for (int i = 0; i < MI; ++i) {
        const uint32_t* pa = As[buf] + (wm + i * 16 + g) * AS + kk + 2 * tg;
        uint2 p0 = *(const uint2*)pa;
        uint2 p1 = *(const uint2*)(pa + 8 * AS);
        af[i][0] = p0.x;
        af[i][1] = p1.x;
        af[i][2] = p0.y;
        af[i][3] = p1.y;
      }
      #pragma unroll
      for (int j = 0; j < NI; ++j) {
        const uint32_t* pb = Bs[buf] + (kk + tg) * BS + wn + j * 8 + g;
        bf[j][0] = pb[0];
        bf[j][1] = pb[4 * BS];
      }
      #pragma unroll
      for (int i = 0; i < MI; ++i)
        #pragma unroll
        for (int j = 0; j < NI; ++j)
          mma_tf32(c[i][j], af[i][0], af[i][1], af[i][2], af[i][3],
                   bf[j][0], bf[j][1]);
    }

    if (more) {
      int nb = buf ^ 1;
      stageA(nb);
      stageB(nb);
    }
    __syncthreads();
  }

  #pragma unroll
  for (int i = 0; i < MI; ++i) {
    int r0 = bm + wm + i * 16 + g;
    #pragma unroll
    for (int j = 0; j < NI; ++j) {
      int col = bn + wn + j * 8 + tg * 2;
      float b0 = bias ? bias[col] : 0.f;
      float b1 = bias ? bias[col + 1] : 0.f;
      float2 v0 = {c[i][j][0] + b0, c[i][j][1] + b1};
      float2 v1 = {c[i][j][2] + b0, c[i][j][3] + b1};
      *(float2*)&C[(size_t)r0 * N + col] = v0;
      *(float2*)&C[(size_t)(r0 + 8) * N + col] = v1;
    }
  }
}

// =================================================================
// Fused attention v3b (round-13 winner): n-tile 128, 512 threads,
// 1 wave, smem aliasing, Vt XOR-swizzled staging.
// =================================================================
#define VT_OFF   0
#define UN_OFF   (64 * 264)
#define KS_OFF   UN_OFF
#define QS_OFF   (UN_OFF + 256 * 68)
#define PS_OFF   UN_OFF
#define ATTN_SMEM_WORDS (UN_OFF + 128 * 260)
#define ATTN_SMEM_BYTES (ATTN_SMEM_WORDS * 4)

__global__ __launch_bounds__(512, 1) void attn_kernel() {
  extern __shared__ uint32_t sm[];
  uint32_t* Vt = sm + VT_OFF;     // [d][m^swz(d)]  stride 264
  uint32_t* Ks = sm + KS_OFF;     // [m][d]  stride 68   (phase 1)
  uint32_t* Qs = sm + QS_OFF;     // [n][d]  stride 68   (phase 1)
  float*    Ps = (float*)(sm + PS_OFF);  // [n][m] stride 260 (phase 2)
  uint32_t* PsU = sm + PS_OFF;

  int t = threadIdx.x;
  int b = blockIdx.y >> 3, h = blockIdx.y & 7;
  int n0 = blockIdx.x * 128;
  int w = t >> 5, l = t & 31;
  int g = l >> 2, tg = l & 3;

  const float* qkvb = g_qkv + (size_t)b * NSEQ * QKV3 + h * DH;

  // ---- phase 1 stage: K [m][d], V transposed+swizzled, Q [n][d] ----
  {
    int c16 = t & 15, r16 = t >> 4;   // r16 0..31
    int d0 = c16 * 4;
    int xrv = (c16 & 7) << 2;         // swizzle for rows d0..d0+3
    #pragma unroll
    for (int i = 0; i < 8; ++i) {
      int m = r16 + i * 32;
      const float* rowp = qkvb + (size_t)m * QKV3;
      float4 k4 = *(const float4*)(rowp + DIMC + d0);
      uint4 ku = {f2tf(k4.x), f2tf(k4.y), f2tf(k4.z), f2tf(k4.w)};
      *(uint4*)&Ks[m * 68 + d0] = ku;
      float4 v4 = *(const float4*)(rowp + 2 * DIMC + d0);
      int col = m ^ xrv;
      Vt[(d0 + 0) * 264 + col] = f2tf(v4.x);
      Vt[(d0 + 1) * 264 + col] = f2tf(v4.y);
      Vt[(d0 + 2) * 264 + col] = f2tf(v4.z);
      Vt[(d0 + 3) * 264 + col] = f2tf(v4.w);
    }
    #pragma unroll
    for (int i = 0; i < 4; ++i) {
      int n = r16 + i * 32;
      const float* rowp = qkvb + (size_t)(n0 + n) * QKV3;
      float4 q4 = *(const float4*)(rowp + d0);
      uint4 qu = {f2tf(q4.x), f2tf(q4.y), f2tf(q4.z), f2tf(q4.w)};
      *(uint4*)&Qs[n * 68 + d0] = qu;
    }
  }
  __syncthreads();

  // ---- scores S[128][256] = Q @ K^T ; warp tile 32x64 ----
  int wm = (w >> 2) * 32;
  int wnn = (w & 3) * 64;
  float s[2][8][4];
  #pragma unroll
  for (int i = 0; i < 2; ++i)
    #pragma unroll
    for (int j = 0; j < 8; ++j)
      #pragma unroll
      for (int q = 0; q < 4; ++q) s[i][j][q] = 0.f;

  #pragma unroll
  for (int kk = 0; kk < 64; kk += 8) {
    uint32_t a[2][4], bf[8][2];
    #pragma unroll
    for (int i = 0; i < 2; ++i) {
      int r0 = wm + i * 16;
      a[i][0] = Qs[(r0 + g) * 68 + kk + tg];
      a[i][1] = Qs[(r0 + g + 8) * 68 + kk + tg];
      a[i][2] = Qs[(r0 + g) * 68 + kk + tg + 4];
      a[i][3] = Qs[(r0 + g + 8) * 68 + kk + tg + 4];
    }
    #pragma unroll
    for (int j = 0; j < 8; ++j) {
      int m0 = wnn + j * 8;
      bf[j][0] = Ks[(m0 + g) * 68 + kk + tg];
      bf[j][1] = Ks[(m0 + g) * 68 + kk + tg + 4];
    }
    #pragma unroll
    for (int i = 0; i < 2; ++i)
      #pragma unroll
      for (int j = 0; j < 8; ++j)
        mma_tf32(s[i][j], a[i][0], a[i][1], a[i][2], a[i][3],
                 bf[j][0], bf[j][1]);
  }
  __syncthreads();   // Ks/Qs reads done; safe to overwrite with Ps

  #pragma unroll
  for (int i = 0; i < 2; ++i) {
    int r0 = wm + i * 16 + g;
    #pragma unroll
    for (int j = 0; j < 8; ++j) {
      int cc = wnn + j * 8 + tg * 2;
      Ps[r0 * 260 + cc]           = s[i][j][0] * SCALE;
      Ps[r0 * 260 + cc + 1]       = s[i][j][1] * SCALE;
      Ps[(r0 + 8) * 260 + cc]     = s[i][j][2] * SCALE;
      Ps[(r0 + 8) * 260 + cc + 1] = s[i][j][3] * SCALE;
    }
  }
  __syncthreads();

  // ---- softmax: 8 rows per warp; attn -> g_attn (fp32) + Ps (tf32) ----
  {
    #pragma unroll
    for (int r = 0; r < 8; ++r) {
      int n = w * 8 + r;
      float* row = &Ps[n * 260];
      float vals[8];
      float vmax = -1e30f;
      #pragma unroll
      for (int i = 0; i < 8; ++i) {
        vals[i] = row[l + i * 32];
        vmax = fmaxf(vmax, vals[i]);
      }
      #pragma unroll
      for (int o = 16; o; o >>= 1)
        vmax = fmaxf(vmax, __shfl_xor_sync(0xffffffffu, vmax, o));
      float ssum = 0.f;
      #pragma unroll
      for (int i = 0; i < 8; ++i) { vals[i] = __expf(vals[i] - vmax); ssum += vals[i]; }
      #pragma unroll
      for (int o = 16; o; o >>= 1) ssum += __shfl_xor_sync(0xffffffffu, ssum, o);
      float inv = 1.f / ssum;
      float* gA = &g_attn[((size_t)(b * 8 + h) * 256 + n0 + n) * 256];
      #pragma unroll
      for (int i = 0; i < 8; ++i) {
        float a = vals[i] * inv;
        gA[l + i * 32] = a;
        PsU[n * 260 + l + i * 32] = f2tf(a);
      }
    }
  }
  __syncthreads();

  // ---- O[128][64] = P @ V ; warp tile 32x16 (Vt reads de-swizzled) ----
  {
    int wd = (w & 3) * 16;
    float oc[2][2][4];
    #pragma unroll
    for (int i = 0; i < 2; ++i)
      #pragma unroll
      for (int j = 0; j < 2; ++j)
        #pragma unroll
        for (int q = 0; q < 4; ++q) oc[i][j][q] = 0.f;

    #pragma unroll 4
    for (int kk = 0; kk < 256; kk += 8) {
      uint32_t a[2][4], bf[2][2];
      #pragma unroll
      for (int i = 0; i < 2; ++i) {
        int r0 = wm + i * 16;
        a[i][0] = PsU[(r0 + g) * 260 + kk + tg];
        a[i][1] = PsU[(r0 + g + 8) * 260 + kk + tg];
        a[i][2] = PsU[(r0 + g) * 260 + kk + tg + 4];
        a[i][3] = PsU[(r0 + g + 8) * 260 + kk + tg + 4];
      }
      #pragma unroll
      for (int j = 0; j < 2; ++j) {
        int dr = wd + j * 8 + g;
        int xr = ((dr >> 2) & 7) << 2;
        bf[j][0] = Vt[dr * 264 + ((kk + tg) ^ xr)];
        bf[j][1] = Vt[dr * 264 + ((kk + tg + 4) ^ xr)];
      }
      #pragma unroll
      for (int i = 0; i < 2; ++i)
        #pragma unroll
        for (int j = 0; j < 2; ++j)
          mma_tf32(oc[i][j], a[i][0], a[i][1], a[i][2], a[i][3],
                   bf[j][0], bf[j][1]);
    }
    #pragma unroll
    for (int i = 0; i < 2; ++i) {
      int n = n0 + wm + i * 16 + g;
      #pragma unroll
      for (int j = 0; j < 2; ++j) {
        int dd = h * 64 + wd + j * 8 + tg * 2;
        float2 v0 = {oc[i][j][0], oc[i][j][1]};
        float2 v1 = {oc[i][j][2], oc[i][j][3]};
        *(float2*)&g_o[(size_t)(b * 256 + n) * 512 + dd] = v0;
        *(float2*)&g_o[(size_t)(b * 256 + n + 8) * 512 + dd] = v1;
      }
    }
  }
}

// =================================================================
// rpos v5 (scalar, proven): g_o += Σ_m attn * T[idx[n,m]]
// =================================================================
__global__ __launch_bounds__(256) void rpos_kernel(
    const float* __restrict__ table, const int* __restrict__ idx_map) {
  int n = blockIdx.x, h = blockIdx.y;
  __shared__ float sAT[256][12];     // [m][b], padded stride 12
  __shared__ int   sIdx[256];
  __shared__ float sPart[8][8][64];  // [warp][b][d]

  int t = threadIdx.x;
  sIdx[t] = idx_map[n * 256 + t];
  #pragma unroll
  for (int b = 0; b < 8; ++b)
    sAT[t][b] = g_attn[((size_t)(b * 8 + h) * 256 + n) * 256 + t];
  __syncthreads();

  int w = t >> 5, l = t & 31;
  int hw = l >> 4, dl = l & 15;
  int base = w * 32 + hw;

  float acc[8][4];
  #pragma unroll
  for (int b = 0; b < 8; ++b)
    #pragma unroll
    for (int q = 0; q < 4; ++q) acc[b][q] = 0.f;

  const float* tb = table + h * DH + dl * 4;

  float4 buf[4];
  #pragma unroll
  for (int i = 0; i < 4; ++i)
    buf[i] = *(const float4*)&tb[(size_t)sIdx[base + 2 * i] * DIMC];

  #pragma unroll
  for (int i = 0; i < 16; ++i) {
    float4 tv = buf[i & 3];
    if (i + 4 < 16)
      buf[i & 3] = *(const float4*)&tb[(size_t)sIdx[base + 2 * (i + 4)] * DIMC];
    int m = base + 2 * i;
    float4 aa0 = *(const float4*)&sAT[m][0];
    float4 aa1 = *(const float4*)&sAT[m][4];
    acc[0][0] += aa0.x * tv.x; acc[0][1] += aa0.x * tv.y;
    acc[0][2] += aa0.x * tv.z; acc[0][3] += aa0.x * tv.w;
    acc[1][0] += aa0.y * tv.x; acc[1][1] += aa0.y * tv.y;
    acc[1][2] += aa0.y * tv.z; acc[1][3] += aa0.y * tv.w;
    acc[2][0] += aa0.z * tv.x; acc[2][1] += aa0.z * tv.y;
    acc[2][2] += aa0.z * tv.z; acc[2][3] += aa0.z * tv.w;
    acc[3][0] += aa0.w * tv.x; acc[3][1] += aa0.w * tv.y;
    acc[3][2] += aa0.w * tv.z; acc[3][3] += aa0.w * tv.w;
    acc[4][0] += aa1.x * tv.x; acc[4][1] += aa1.x * tv.y;
    acc[4][2] += aa1.x * tv.z; acc[4][3] += aa1.x * tv.w;
    acc[5][0] += aa1.y * tv.x; acc[5][1] += aa1.y * tv.y;
    acc[5][2] += aa1.y * tv.z; acc[5][3] += aa1.y * tv.w;
    acc[6][0] += aa1.z * tv.x; acc[6][1] += aa1.z * tv.y;
    acc[6][2] += aa1.z * tv.z; acc[6][3] += aa1.z * tv.w;
    acc[7][0] += aa1.w * tv.x; acc[7][1] += aa1.w * tv.y;
    acc[7][2] += aa1.w * tv.z; acc[7][3] += aa1.w * tv.w;
  }

  #pragma unroll
  for (int b = 0; b < 8; ++b)
    #pragma unroll
    for (int q = 0; q < 4; ++q)
      acc[b][q] += __shfl_xor_sync(0xffffffffu, acc[b][q], 16);

  if (hw == 0) {
    #pragma unroll
    for (int b = 0; b < 8; ++b) {
      float4 v = {acc[b][0], acc[b][1], acc[b][2], acc[b][3]};
      *(float4*)&sPart[w][b][dl * 4] = v;
    }
  }
  __syncthreads();

  #pragma unroll
  for (int o = t; o < 512; o += 256) {
    int b = o >> 6, d = o & 63;
    float s2 = 0.f;
    #pragma unroll
    for (int w2 = 0; w2 < 8; ++w2) s2 += sPart[w2][b][d];
    g_o[(size_t)(b * 256 + n) * 512 + h * 64 + d] += s2;
  }
}

// =================================================================
extern "C" void kernel_launch(void* const* d_in, const int* in_sizes, int n_in,
                              void* d_out, int out_size) {
  const float* x      = (const float*)d_in[0];
  const float* ln_g   = (const float*)d_in[1];
  const float* ln_b   = (const float*)d_in[2];
  const float* w_qkv  = (const float*)d_in[3];
  const float* table  = (const float*)d_in[4];
  const float* w_out  = (const float*)d_in[5];
  const float* b_out  = (const float*)d_in[6];
  const int*   idxmap = (const int*)d_in[7];
  float* out = (float*)d_out;

  cudaFuncSetAttribute(attn_kernel, cudaFuncAttributeMaxDynamicSharedMemorySize,
                       ATTN_SMEM_BYTES);

  void *p_xn, *p_qkv, *p_o;
  cudaGetSymbolAddress(&p_xn, g_xn);
  cudaGetSymbolAddress(&p_qkv, g_qkv);
  cudaGetSymbolAddress(&p_o, g_o);

  // 1. LayerNorm
  ln_kernel<<<NTOK, 256>>>(x, ln_g, ln_b);

  // 2. qkv = xn @ w_qkv   (2048 x 1536 x 512), BM=128 BN=128
  gemm_tf32<128, 128, 2, 4><<<dim3(QKV3 / 128, NTOK / 128), 256>>>(
      (const float*)p_xn, w_qkv, nullptr, (float*)p_qkv, NTOK, QKV3, DIMC);

  // 3. attention (scores, softmax, attn·V), n-tile 128 -> 1 wave
  attn_kernel<<<dim3(2, NB * NHEADS), 512, ATTN_SMEM_BYTES>>>();

  // 4. relative-position contribution (scalar v5)
  rpos_kernel<<<dim3(NSEQ, NHEADS), 256>>>(table, idxmap);

  // 5. out = g_o @ w_out + b_out   (2048 x 512 x 512), BM=64 BN=64
  //    grid 256 blocks, ~21.5KB smem -> 2 blocks/SM
  gemm_tf32<64, 64, 2, 4><<<dim3(DIMC / 64, NTOK / 64), 256>>>(
      (const float*)p_o, w_out, b_out, out, NTOK, DIMC, DIMC);
}